// round 12
// baseline (speedup 1.0000x reference)
#include <cuda_runtime.h>

// y[i,o,n] = sum_{j,k} x[j,(o-1)%28,n+k-1]*W[i,j,0,k] + x[j,(o-2)%28,n+k-1]*W[i,j,1,k]
// x:(64,28,28) f32, W:(128,64,2,3) f32, y:(128,28,28) f32, zero-pad over n.
//
// ONE kernel. Block = 4 ch x 2 o-rows x 28 n; 8 warps, warp w owns j in [8w,8w+8)
// (no cross-warp LDS redundancy). Partials reduced in-block through smem.
// Grid (32,14) = 448 blocks x 256 thr, 38.4KB smem, <=64 regs -> 4 blocks/SM,
// all blocks resident in one wave (~24 warps/SM). Math: packed fma.rn.f32x2.

typedef unsigned long long u64;

static __device__ __forceinline__ u64 pk2(float a, float b) {
    u64 r; asm("mov.b64 %0, {%1, %2};" : "=l"(r) : "f"(a), "f"(b)); return r;
}
static __device__ __forceinline__ void up2(float& a, float& b, u64 v) {
    asm("mov.b64 {%0, %1}, %2;" : "=f"(a), "=f"(b) : "l"(v));
}
static __device__ __forceinline__ void fma2(u64& d, u64 a, u64 b) {
    asm("fma.rn.f32x2 %0, %1, %2, %0;" : "+l"(d) : "l"(a), "l"(b));
}
static __device__ __forceinline__ u64 lds64(unsigned sa) {
    u64 r; asm("ld.shared.b64 %0, [%1];" : "=l"(r) : "r"(sa)); return r;
}
static __device__ __forceinline__ void lds128_2x64(u64& a, u64& b, unsigned sa) {
    asm("ld.shared.v2.b64 {%0, %1}, [%2];" : "=l"(a), "=l"(b) : "r"(sa));
}

#define NJW 8   // j per warp
#define NW  8   // warps per block
#define ICB 4   // channels per block
// block output tile: ICB x 2 o-rows x 28 n = 224 floats

__global__ __launch_bounds__(256, 4)
void conv_one_kernel(const float* __restrict__ x,
                     const float* __restrict__ W,
                     float* __restrict__ out) {
    // x: 3 rows per j (global rows ob-2, ob-1, ob), padded: col n -> slot n+1,
    // slots 0 and 29..33 zeroed. Row stride 34 de-phases banks.
    __shared__ __align__(16) float xs[64][3][34];     // 26112 B
    // duplicated weight pairs ws2[j][c][2m..2m+1] = (w,w), m = l*3+k
    __shared__ __align__(16) float ws2[64][ICB][12];  // 12288 B
    float* pred = &xs[0][0][0];  // reused after mainloop: [NW][224]

    const int tid = threadIdx.x;
    const int ib = blockIdx.x * ICB;   // 0..124
    const int ob = blockIdx.y * 2;     // 0..26

    // zero pad slots (0 and 29..33) per (j,row)
    for (int i = tid; i < 64 * 3; i += 256) {
        int j = i / 3, rl = i - j * 3;
        float* r = &xs[j][rl][0];
        r[0] = 0.f; r[29] = 0.f; r[30] = 0.f; r[31] = 0.f; r[32] = 0.f; r[33] = 0.f;
    }
    // stage x: 64 j x 3 rows x 7 float4 = 1344 float4 loads
    #pragma unroll
    for (int q = 0; q < 6; q++) {
        int idx4 = tid + 256 * q;
        if (idx4 < 1344) {
            int j   = idx4 / 21;
            int rem = idx4 - j * 21;
            int rl  = rem / 7;
            int n4  = rem - rl * 7;
            int row = ob - 2 + rl;
            if (row < 0) row += 28;
            float4 v = *reinterpret_cast<const float4*>(x + j * 784 + row * 28 + 4 * n4);
            float* d = &xs[j][rl][1 + 4 * n4];
            d[0] = v.x; d[1] = v.y; d[2] = v.z; d[3] = v.w;
        }
    }
    // stage weights: 4c x 64j x 6m = 1536 = 6*256 exactly
    #pragma unroll
    for (int q = 0; q < 6; q++) {
        int idx = tid + 256 * q;
        int c   = idx / 384;
        int rem = idx - c * 384;
        int j   = rem / 6;
        int m   = rem - j * 6;
        float w = W[(ib + c) * 384 + j * 6 + m];
        ws2[j][c][2 * m]     = w;
        ws2[j][c][2 * m + 1] = w;
    }
    __syncthreads();

    const int warp = tid >> 5;
    const int lane = tid & 31;
    const int ol = lane & 1;       // o-row within block
    const int ng = lane >> 1;      // 0..15; ng>=14 redundant (masked at store)
    const int n0 = 2 * ng;         // first output col of this thread's pair

    const unsigned xs_sa = (unsigned)__cvta_generic_to_shared(&xs[0][0][0]);
    const unsigned ws_sa = (unsigned)__cvta_generic_to_shared(&ws2[0][0][0]);

    u64 acc[ICB];
    #pragma unroll
    for (int c = 0; c < ICB; c++) acc[c] = 0ULL;

    const int j0 = warp * NJW;
    #pragma unroll
    for (int t = 0; t < NJW; t++) {
        const int j = j0 + t;
        // out row o = ob+ol: row (o-1) -> rl = ol+1 (l=0 weights); row (o-2) -> rl = ol (l=1)
        const unsigned r1 = xs_sa + (unsigned)(((j * 3 + ol + 1) * 34 + n0) * 4);
        const unsigned r2 = xs_sa + (unsigned)(((j * 3 + ol) * 34 + n0) * 4);

        u64 A0 = lds64(r1), A2 = lds64(r1 + 8);   // slots (n0,n0+1), (n0+2,n0+3)
        u64 B0 = lds64(r2), B2 = lds64(r2 + 8);
        float a0, a1, a2, a3, b0, b1, b2, b3;
        up2(a0, a1, A0); up2(a2, a3, A2);
        up2(b0, b1, B0); up2(b2, b3, B2);
        u64 A1 = pk2(a1, a2), B1 = pk2(b1, b2);   // slots (n0+1, n0+2)

        #pragma unroll
        for (int c = 0; c < ICB; c++) {
            const unsigned wsa = ws_sa + (unsigned)(((j * ICB + c) * 12) * 4);
            u64 w0, w1, w2, w3, w4, w5;            // warp-uniform -> broadcast LDS
            lds128_2x64(w0, w1, wsa);              // l0k0, l0k1
            lds128_2x64(w2, w3, wsa + 16);         // l0k2, l1k0
            lds128_2x64(w4, w5, wsa + 32);         // l1k1, l1k2
            // k-tap pair for k over out cols (n0,n0+1): slots (n0+k, n0+k+1)
            fma2(acc[c], A0, w0);
            fma2(acc[c], A1, w1);
            fma2(acc[c], A2, w2);
            fma2(acc[c], B0, w3);
            fma2(acc[c], B1, w4);
            fma2(acc[c], B2, w5);
        }
    }

    __syncthreads();   // all xs reads complete; safe to overwrite with partials

    if (ng < 14) {
        #pragma unroll
        for (int c = 0; c < ICB; c++) {
            float lo, hi; up2(lo, hi, acc[c]);
            float2 v = make_float2(lo, hi);
            *reinterpret_cast<float2*>(&pred[warp * 224 + (c * 2 + ol) * 28 + n0]) = v;
        }
    }
    __syncthreads();

    if (tid < 224) {
        float s = 0.f;
        #pragma unroll
        for (int w = 0; w < NW; w++) s += pred[w * 224 + tid];  // stride 224%32==0: conflict-free
        int c   = tid / 56;
        int rem = tid - c * 56;
        int o2  = rem / 28;
        int n   = rem - o2 * 28;
        out[(ib + c) * 784 + (ob + o2) * 28 + n] = s;
    }
}

extern "C" void kernel_launch(void* const* d_in, const int* in_sizes, int n_in,
                              void* d_out, int out_size) {
    const float* x = (const float*)d_in[0];  // (1,64,28,28)  = 50176 f32
    const float* W = (const float*)d_in[1];  // (128,64,2,3) = 147456 f32
    float* out = (float*)d_out;              // (1,128,28,28) = 100352 f32

    dim3 grid(32, 14);  // (i-groups of 4, o-groups of 2) = 448 blocks, one wave
    conv_one_kernel<<<grid, 256>>>(x, W, out);
}

// round 13
// speedup vs baseline: 1.1045x; 1.1045x over previous
#include <cuda_runtime.h>

// y[i,o,n] = sum_{j,k} x[j,(o-1)%28,n+k-1]*W[i,j,0,k] + x[j,(o-2)%28,n+k-1]*W[i,j,1,k]
// x:(64,28,28) f32, W:(128,64,2,3) f32, y:(128,28,28) f32, zero-pad over n.
//
// ONE kernel. Block = 4 ch x 2 o-rows x 28 n; 8 warps, warp w owns j in [8w,8w+8)
// (no cross-warp LDS redundancy). Partials reduced in-block through smem.
// Grid (32,14) = 448 blocks x 256 thr, 38.4KB smem, <=64 regs -> 4 blocks/SM,
// all blocks resident in one wave (~24 warps/SM). Math: packed fma.rn.f32x2.

typedef unsigned long long u64;

static __device__ __forceinline__ u64 pk2(float a, float b) {
    u64 r; asm("mov.b64 %0, {%1, %2};" : "=l"(r) : "f"(a), "f"(b)); return r;
}
static __device__ __forceinline__ void up2(float& a, float& b, u64 v) {
    asm("mov.b64 {%0, %1}, %2;" : "=f"(a), "=f"(b) : "l"(v));
}
static __device__ __forceinline__ void fma2(u64& d, u64 a, u64 b) {
    asm("fma.rn.f32x2 %0, %1, %2, %0;" : "+l"(d) : "l"(a), "l"(b));
}
static __device__ __forceinline__ u64 lds64(unsigned sa) {
    u64 r; asm("ld.shared.b64 %0, [%1];" : "=l"(r) : "r"(sa)); return r;
}
static __device__ __forceinline__ void lds128_2x64(u64& a, u64& b, unsigned sa) {
    asm("ld.shared.v2.b64 {%0, %1}, [%2];" : "=l"(a), "=l"(b) : "r"(sa));
}

#define NJW 8   // j per warp
#define NW  8   // warps per block
#define ICB 4   // channels per block
// block output tile: ICB x 2 o-rows x 28 n = 224 floats

__global__ __launch_bounds__(256, 4)
void conv_one_kernel(const float* __restrict__ x,
                     const float* __restrict__ W,
                     float* __restrict__ out) {
    // x: 3 rows per j (global rows ob-2, ob-1, ob), padded: col n -> slot n+1,
    // slots 0 and 29..33 zeroed. Row stride 34 de-phases banks.
    __shared__ __align__(16) float xs[64][3][34];     // 26112 B
    // duplicated weight pairs ws2[j][c][2m..2m+1] = (w,w), m = l*3+k
    __shared__ __align__(16) float ws2[64][ICB][12];  // 12288 B
    float* pred = &xs[0][0][0];  // reused after mainloop: [NW][224]

    const int tid = threadIdx.x;
    const int ib = blockIdx.x * ICB;   // 0..124
    const int ob = blockIdx.y * 2;     // 0..26

    // zero pad slots (0 and 29..33) per (j,row)
    for (int i = tid; i < 64 * 3; i += 256) {
        int j = i / 3, rl = i - j * 3;
        float* r = &xs[j][rl][0];
        r[0] = 0.f; r[29] = 0.f; r[30] = 0.f; r[31] = 0.f; r[32] = 0.f; r[33] = 0.f;
    }
    // stage x: 64 j x 3 rows x 7 float4 = 1344 float4 loads
    #pragma unroll
    for (int q = 0; q < 6; q++) {
        int idx4 = tid + 256 * q;
        if (idx4 < 1344) {
            int j   = idx4 / 21;
            int rem = idx4 - j * 21;
            int rl  = rem / 7;
            int n4  = rem - rl * 7;
            int row = ob - 2 + rl;
            if (row < 0) row += 28;
            float4 v = *reinterpret_cast<const float4*>(x + j * 784 + row * 28 + 4 * n4);
            float* d = &xs[j][rl][1 + 4 * n4];
            d[0] = v.x; d[1] = v.y; d[2] = v.z; d[3] = v.w;
        }
    }
    // stage weights: 4c x 64j x 6m = 1536 = 6*256 exactly
    #pragma unroll
    for (int q = 0; q < 6; q++) {
        int idx = tid + 256 * q;
        int c   = idx / 384;
        int rem = idx - c * 384;
        int j   = rem / 6;
        int m   = rem - j * 6;
        float w = W[(ib + c) * 384 + j * 6 + m];
        ws2[j][c][2 * m]     = w;
        ws2[j][c][2 * m + 1] = w;
    }
    __syncthreads();

    const int warp = tid >> 5;
    const int lane = tid & 31;
    const int ol = lane & 1;       // o-row within block
    const int ng = lane >> 1;      // 0..15; ng>=14 redundant (masked at store)
    const int n0 = 2 * ng;         // first output col of this thread's pair

    const unsigned xs_sa = (unsigned)__cvta_generic_to_shared(&xs[0][0][0]);
    const unsigned ws_sa = (unsigned)__cvta_generic_to_shared(&ws2[0][0][0]);

    u64 acc[ICB];
    #pragma unroll
    for (int c = 0; c < ICB; c++) acc[c] = 0ULL;

    const int j0 = warp * NJW;
    #pragma unroll
    for (int t = 0; t < NJW; t++) {
        const int j = j0 + t;
        // out row o = ob+ol: row (o-1) -> rl = ol+1 (l=0 weights); row (o-2) -> rl = ol (l=1)
        const unsigned r1 = xs_sa + (unsigned)(((j * 3 + ol + 1) * 34 + n0) * 4);
        const unsigned r2 = xs_sa + (unsigned)(((j * 3 + ol) * 34 + n0) * 4);

        u64 A0 = lds64(r1), A2 = lds64(r1 + 8);   // slots (n0,n0+1), (n0+2,n0+3)
        u64 B0 = lds64(r2), B2 = lds64(r2 + 8);
        float a0, a1, a2, a3, b0, b1, b2, b3;
        up2(a0, a1, A0); up2(a2, a3, A2);
        up2(b0, b1, B0); up2(b2, b3, B2);
        u64 A1 = pk2(a1, a2), B1 = pk2(b1, b2);   // slots (n0+1, n0+2)

        #pragma unroll
        for (int c = 0; c < ICB; c++) {
            const unsigned wsa = ws_sa + (unsigned)(((j * ICB + c) * 12) * 4);
            u64 w0, w1, w2, w3, w4, w5;            // warp-uniform -> broadcast LDS
            lds128_2x64(w0, w1, wsa);              // l0k0, l0k1
            lds128_2x64(w2, w3, wsa + 16);         // l0k2, l1k0
            lds128_2x64(w4, w5, wsa + 32);         // l1k1, l1k2
            // k-tap pair for k over out cols (n0,n0+1): slots (n0+k, n0+k+1)
            fma2(acc[c], A0, w0);
            fma2(acc[c], A1, w1);
            fma2(acc[c], A2, w2);
            fma2(acc[c], B0, w3);
            fma2(acc[c], B1, w4);
            fma2(acc[c], B2, w5);
        }
    }

    __syncthreads();   // all xs reads complete; safe to overwrite with partials

    if (ng < 14) {
        #pragma unroll
        for (int c = 0; c < ICB; c++) {
            float lo, hi; up2(lo, hi, acc[c]);
            float2 v = make_float2(lo, hi);
            *reinterpret_cast<float2*>(&pred[warp * 224 + (c * 2 + ol) * 28 + n0]) = v;
        }
    }
    __syncthreads();

    if (tid < 224) {
        float s = 0.f;
        #pragma unroll
        for (int w = 0; w < NW; w++) s += pred[w * 224 + tid];  // stride 224%32==0: conflict-free
        int c   = tid / 56;
        int rem = tid - c * 56;
        int o2  = rem / 28;
        int n   = rem - o2 * 28;
        out[(ib + c) * 784 + (ob + o2) * 28 + n] = s;
    }
}

extern "C" void kernel_launch(void* const* d_in, const int* in_sizes, int n_in,
                              void* d_out, int out_size) {
    const float* x = (const float*)d_in[0];  // (1,64,28,28)  = 50176 f32
    const float* W = (const float*)d_in[1];  // (128,64,2,3) = 147456 f32
    float* out = (float*)d_out;              // (1,128,28,28) = 100352 f32

    dim3 grid(32, 14);  // (i-groups of 4, o-groups of 2) = 448 blocks, one wave
    conv_one_kernel<<<grid, 256>>>(x, W, out);
}